// round 2
// baseline (speedup 1.0000x reference)
#include <cuda_runtime.h>
#include <cstdint>

// Problem constants
#define T_   4096
#define H_   2048
#define I_   2816
#define E_   8
#define K_   2
#define TK_  (T_ * K_)

#define BK_   16
#define SSTR_ 20   // smem row stride (BK + 4 pad) -> conflict-free for mma frag pattern

// ---------------- scratch (device globals; no allocs allowed) ----------------
__device__ int   g_counts[E_];
__device__ int   g_cursors[E_];
__device__ int   g_offsets[E_];
__device__ int   g_ids_is32;                          // 1 if topk_ids buffer is int32
__device__ int   g_rowmap[TK_];                       // grouped pos -> flat slot (t*K+k)
__device__ float g_act [(size_t)TK_ * I_];            // silu(gate)*up, grouped rows
__device__ float g_ybuf[(size_t)TK_ * H_];            // per-slot weighted y

// ---------------- routing ----------------
__global__ void k_zero() {
    int i = threadIdx.x;
    if (i < E_) { g_counts[i] = 0; g_cursors[i] = 0; }
    if (i == 0) g_ids_is32 = 0;
}

// Detect ids dtype. Reads only the first TK_ int32 words (32KB) — in bounds
// for both int32 (exactly the buffer) and int64 (first half) layouts.
// int64 little-endian with values 0..7 => every odd int32 word is 0.
// int32 values 0..7 => some odd word nonzero w.p. 1 - 8^-4096.
__global__ void k_detect(const int* __restrict__ idsv) {
    int any = 0;
    for (int i = threadIdx.x * 2 + 1; i < TK_; i += 2 * blockDim.x) any |= idsv[i];
    if (any) atomicOr(&g_ids_is32, 1);
}

__device__ __forceinline__ int load_id(const void* ids, int i, int is32) {
    return is32 ? ((const int*)ids)[i] : (int)((const long long*)ids)[i];
}

__global__ void k_count(const void* __restrict__ ids) {
    int i = blockIdx.x * blockDim.x + threadIdx.x;
    int is32 = g_ids_is32;
    if (i < TK_) atomicAdd(&g_counts[load_id(ids, i, is32)], 1);
}

__global__ void k_offsets() {
    if (threadIdx.x == 0) {
        int acc = 0;
        for (int e = 0; e < E_; e++) { g_offsets[e] = acc; acc += g_counts[e]; }
    }
}

__global__ void k_scatter(const void* __restrict__ ids) {
    int i = blockIdx.x * blockDim.x + threadIdx.x;
    int is32 = g_ids_is32;
    if (i < TK_) {
        int e = load_id(ids, i, is32);
        int pos = g_offsets[e] + atomicAdd(&g_cursors[e], 1);
        g_rowmap[pos] = i;
    }
}

// ---------------- tf32 mma helpers ----------------
__device__ __forceinline__ uint32_t f2tf(float f) {
    uint32_t u;
    asm("cvt.rna.tf32.f32 %0, %1;" : "=r"(u) : "f"(f));
    return u;
}

__device__ __forceinline__ void mma8(float* d, const uint32_t* a, const uint32_t* b) {
    asm volatile(
        "mma.sync.aligned.m16n8k8.row.col.f32.tf32.tf32.f32 "
        "{%0,%1,%2,%3}, {%4,%5,%6,%7}, {%8,%9}, {%0,%1,%2,%3};"
        : "+f"(d[0]), "+f"(d[1]), "+f"(d[2]), "+f"(d[3])
        : "r"(a[0]), "r"(a[1]), "r"(a[2]), "r"(a[3]), "r"(b[0]), "r"(b[1]));
}

__device__ __forceinline__ void cvt_store4(uint32_t* sdst, float4 v) {
    uint4 u;
    u.x = f2tf(v.x); u.y = f2tf(v.y); u.z = f2tf(v.z); u.w = f2tf(v.w);
    *reinterpret_cast<uint4*>(sdst) = u;
}

// ---------------- GEMM1: act = silu(x@Wg^T) * (x@Wu^T), grouped rows ----------------
// A: gathered x rows [cnt x H]  (row-major, K-major)
// B: w13[e]           [2I x H]  (row-major, K-major) -> gate rows [0,I), up rows [I,2I)
// Tile: BM=128, BN=128 (i-dim), BK=16. 256 threads, 8 warps (2m x 4n), warp tile 64x32.
__global__ __launch_bounds__(256, 1)
void k_gemm13(const float* __restrict__ x, const float* __restrict__ w13) {
    __shared__ uint32_t sA[128 * SSTR_];
    __shared__ uint32_t sG[128 * SSTR_];
    __shared__ uint32_t sU[128 * SSTR_];

    const int e   = blockIdx.z;
    const int cnt = g_counts[e];
    const int m0  = blockIdx.y * 128;
    if (m0 >= cnt) return;
    const int off = g_offsets[e];
    const int n0  = blockIdx.x * 128;

    const float* wg = w13 + (size_t)e * (2 * I_) * H_ + (size_t)n0 * H_;
    const float* wu = wg + (size_t)I_ * H_;

    const int tid  = threadIdx.x;
    const int warp = tid >> 5, lane = tid & 31;
    const int wm = (warp >> 2) * 64;
    const int wn = (warp & 3) * 32;

    // Per-thread load assignments: f = tid + j*256, row = f>>2, col4 = f&3
    const float* aptr[2]; const float* gptr[2]; const float* uptr[2];
    int srow[2];
    #pragma unroll
    for (int j = 0; j < 2; j++) {
        int f = tid + j * 256;
        int r = f >> 2, c4 = f & 3;
        srow[j] = r * SSTR_ + c4 * 4;
        int pos = m0 + r;
        if (pos < cnt) {
            int tok = g_rowmap[off + pos] >> 1;          // K_=2
            aptr[j] = x + (size_t)tok * H_ + c4 * 4;
        } else {
            aptr[j] = nullptr;
        }
        gptr[j] = wg + (size_t)r * H_ + c4 * 4;
        uptr[j] = wu + (size_t)r * H_ + c4 * 4;
    }

    float gacc[4][4][4], uacc[4][4][4];
    #pragma unroll
    for (int a = 0; a < 4; a++)
        #pragma unroll
        for (int b = 0; b < 4; b++)
            #pragma unroll
            for (int c = 0; c < 4; c++) { gacc[a][b][c] = 0.f; uacc[a][b][c] = 0.f; }

    float4 ra[2], rg[2], ru[2];
    #pragma unroll
    for (int j = 0; j < 2; j++) {
        ra[j] = aptr[j] ? *reinterpret_cast<const float4*>(aptr[j]) : make_float4(0, 0, 0, 0);
        rg[j] = *reinterpret_cast<const float4*>(gptr[j]);
        ru[j] = *reinterpret_cast<const float4*>(uptr[j]);
    }

    const int KT = H_ / BK_;
    for (int kt = 0; kt < KT; kt++) {
        #pragma unroll
        for (int j = 0; j < 2; j++) {
            cvt_store4(&sA[srow[j]], ra[j]);
            cvt_store4(&sG[srow[j]], rg[j]);
            cvt_store4(&sU[srow[j]], ru[j]);
        }
        __syncthreads();

        if (kt + 1 < KT) {
            int kk = (kt + 1) * BK_;
            #pragma unroll
            for (int j = 0; j < 2; j++) {
                ra[j] = aptr[j] ? *reinterpret_cast<const float4*>(aptr[j] + kk)
                                : make_float4(0, 0, 0, 0);
                rg[j] = *reinterpret_cast<const float4*>(gptr[j] + kk);
                ru[j] = *reinterpret_cast<const float4*>(uptr[j] + kk);
            }
        }

        #pragma unroll
        for (int ks = 0; ks < 2; ks++) {
            const int kb = ks * 8;
            uint32_t af[4][4];
            #pragma unroll
            for (int mf = 0; mf < 4; mf++) {
                int r = wm + mf * 16 + (lane >> 2);
                int c = kb + (lane & 3);
                af[mf][0] = sA[r * SSTR_ + c];
                af[mf][1] = sA[(r + 8) * SSTR_ + c];
                af[mf][2] = sA[r * SSTR_ + c + 4];
                af[mf][3] = sA[(r + 8) * SSTR_ + c + 4];
            }
            #pragma unroll
            for (int nf = 0; nf < 4; nf++) {
                int n = wn + nf * 8 + (lane >> 2);
                int c = kb + (lane & 3);
                uint32_t bg[2], bu[2];
                bg[0] = sG[n * SSTR_ + c]; bg[1] = sG[n * SSTR_ + c + 4];
                bu[0] = sU[n * SSTR_ + c]; bu[1] = sU[n * SSTR_ + c + 4];
                #pragma unroll
                for (int mf = 0; mf < 4; mf++) {
                    mma8(gacc[mf][nf], af[mf], bg);
                    mma8(uacc[mf][nf], af[mf], bu);
                }
            }
        }
        __syncthreads();
    }

    // Epilogue: act = silu(gate) * up
    const int rows_left = cnt - m0;
    #pragma unroll
    for (int mf = 0; mf < 4; mf++) {
        #pragma unroll
        for (int half = 0; half < 2; half++) {
            int r = wm + mf * 16 + (lane >> 2) + half * 8;
            if (r < rows_left) {
                size_t base = (size_t)(off + m0 + r) * I_ + n0 + wn;
                #pragma unroll
                for (int nf = 0; nf < 4; nf++) {
                    float g0 = gacc[mf][nf][half * 2 + 0];
                    float g1 = gacc[mf][nf][half * 2 + 1];
                    float u0 = uacc[mf][nf][half * 2 + 0];
                    float u1 = uacc[mf][nf][half * 2 + 1];
                    float a0 = g0 / (1.f + __expf(-g0)) * u0;
                    float a1 = g1 / (1.f + __expf(-g1)) * u1;
                    int c = nf * 8 + (lane & 3) * 2;
                    *reinterpret_cast<float2*>(g_act + base + c) = make_float2(a0, a1);
                }
            }
        }
    }
}

// ---------------- GEMM2: ybuf[slot] = topk_w[slot] * (act @ w2[e]^T) ----------------
// A: g_act grouped rows [cnt x I]; B: w2[e] [H x I] (K-major). BM=BN=128, BK=16.
__global__ __launch_bounds__(256, 1)
void k_gemm2(const float* __restrict__ w2, const float* __restrict__ tw) {
    __shared__ uint32_t sA[128 * SSTR_];
    __shared__ uint32_t sB[128 * SSTR_];

    const int e   = blockIdx.z;
    const int cnt = g_counts[e];
    const int m0  = blockIdx.y * 128;
    if (m0 >= cnt) return;
    const int off = g_offsets[e];
    const int n0  = blockIdx.x * 128;

    const float* wb = w2 + (size_t)e * H_ * I_ + (size_t)n0 * I_;

    const int tid  = threadIdx.x;
    const int warp = tid >> 5, lane = tid & 31;
    const int wm = (warp >> 2) * 64;
    const int wn = (warp & 3) * 32;

    const float* aptr[2]; const float* bptr[2];
    int srow[2];
    #pragma unroll
    for (int j = 0; j < 2; j++) {
        int f = tid + j * 256;
        int r = f >> 2, c4 = f & 3;
        srow[j] = r * SSTR_ + c4 * 4;
        int pos = m0 + r;
        aptr[j] = (pos < cnt) ? (g_act + (size_t)(off + pos) * I_ + c4 * 4) : nullptr;
        bptr[j] = wb + (size_t)r * I_ + c4 * 4;
    }

    float acc[4][4][4];
    #pragma unroll
    for (int a = 0; a < 4; a++)
        #pragma unroll
        for (int b = 0; b < 4; b++)
            #pragma unroll
            for (int c = 0; c < 4; c++) acc[a][b][c] = 0.f;

    float4 ra[2], rb[2];
    #pragma unroll
    for (int j = 0; j < 2; j++) {
        ra[j] = aptr[j] ? *reinterpret_cast<const float4*>(aptr[j]) : make_float4(0, 0, 0, 0);
        rb[j] = *reinterpret_cast<const float4*>(bptr[j]);
    }

    const int KT = I_ / BK_;
    for (int kt = 0; kt < KT; kt++) {
        #pragma unroll
        for (int j = 0; j < 2; j++) {
            cvt_store4(&sA[srow[j]], ra[j]);
            cvt_store4(&sB[srow[j]], rb[j]);
        }
        __syncthreads();

        if (kt + 1 < KT) {
            int kk = (kt + 1) * BK_;
            #pragma unroll
            for (int j = 0; j < 2; j++) {
                ra[j] = aptr[j] ? *reinterpret_cast<const float4*>(aptr[j] + kk)
                                : make_float4(0, 0, 0, 0);
                rb[j] = *reinterpret_cast<const float4*>(bptr[j] + kk);
            }
        }

        #pragma unroll
        for (int ks = 0; ks < 2; ks++) {
            const int kb = ks * 8;
            uint32_t af[4][4];
            #pragma unroll
            for (int mf = 0; mf < 4; mf++) {
                int r = wm + mf * 16 + (lane >> 2);
                int c = kb + (lane & 3);
                af[mf][0] = sA[r * SSTR_ + c];
                af[mf][1] = sA[(r + 8) * SSTR_ + c];
                af[mf][2] = sA[r * SSTR_ + c + 4];
                af[mf][3] = sA[(r + 8) * SSTR_ + c + 4];
            }
            #pragma unroll
            for (int nf = 0; nf < 4; nf++) {
                int n = wn + nf * 8 + (lane >> 2);
                int c = kb + (lane & 3);
                uint32_t bf[2];
                bf[0] = sB[n * SSTR_ + c]; bf[1] = sB[n * SSTR_ + c + 4];
                #pragma unroll
                for (int mf = 0; mf < 4; mf++) mma8(acc[mf][nf], af[mf], bf);
            }
        }
        __syncthreads();
    }

    const int rows_left = cnt - m0;
    #pragma unroll
    for (int mf = 0; mf < 4; mf++) {
        #pragma unroll
        for (int half = 0; half < 2; half++) {
            int r = wm + mf * 16 + (lane >> 2) + half * 8;
            if (r < rows_left) {
                int slot = g_rowmap[off + m0 + r];
                float w = tw[slot];
                size_t base = (size_t)slot * H_ + n0 + wn;
                #pragma unroll
                for (int nf = 0; nf < 4; nf++) {
                    float y0 = acc[mf][nf][half * 2 + 0] * w;
                    float y1 = acc[mf][nf][half * 2 + 1] * w;
                    int c = nf * 8 + (lane & 3) * 2;
                    *reinterpret_cast<float2*>(g_ybuf + base + c) = make_float2(y0, y1);
                }
            }
        }
    }
}

// ---------------- combine: out[t] = ybuf[2t] + ybuf[2t+1] (tw already applied) -------
__global__ void k_combine(float* __restrict__ out) {
    int i = blockIdx.x * blockDim.x + threadIdx.x;       // over T*H/4
    const int HW4 = H_ / 4;
    if (i < T_ * HW4) {
        int t = i / HW4, h4 = i % HW4;
        const float4* yb = reinterpret_cast<const float4*>(g_ybuf);
        float4 y0 = yb[(size_t)(2 * t) * HW4 + h4];
        float4 y1 = yb[(size_t)(2 * t + 1) * HW4 + h4];
        float4 o;
        o.x = y0.x + y1.x; o.y = y0.y + y1.y; o.z = y0.z + y1.z; o.w = y0.w + y1.w;
        reinterpret_cast<float4*>(out)[i] = o;
    }
}

// ---------------- launch ----------------
extern "C" void kernel_launch(void* const* d_in, const int* in_sizes, int n_in,
                              void* d_out, int out_size) {
    const float* x   = (const float*)d_in[0];
    const float* w13 = (const float*)d_in[1];
    const float* w2  = (const float*)d_in[2];
    const float* tw  = (const float*)d_in[3];
    const void*  ids = d_in[4];                 // int32 or int64, detected on device
    float* out = (float*)d_out;

    k_zero<<<1, 32>>>();
    k_detect<<<1, 256>>>((const int*)ids);
    k_count<<<TK_ / 256, 256>>>(ids);
    k_offsets<<<1, 32>>>();
    k_scatter<<<TK_ / 256, 256>>>(ids);

    dim3 g13(I_ / 128, TK_ / 128, E_);   // (22, 64, 8), inactive m-tiles exit early
    k_gemm13<<<g13, 256>>>(x, w13);

    dim3 g2(H_ / 128, TK_ / 128, E_);    // (16, 64, 8)
    k_gemm2<<<g2, 256>>>(w2, tw);

    k_combine<<<(T_ * (H_ / 4) + 255) / 256, 256>>>(out);
}

// round 4
// speedup vs baseline: 2.1293x; 2.1293x over previous
#include <cuda_runtime.h>
#include <cuda_fp16.h>
#include <cstdint>

// Problem constants
#define T_   4096
#define H_   2048
#define I_   2816
#define E_   8
#define K_   2
#define TK_  (T_ * K_)

#define BK_   32            // k per mainloop iter (fp16 elements)
#define STR_  20            // smem row stride in 32-bit words (16 data words + 4 pad)
#define TILEW (128 * STR_)  // words per 128-row tile buffer

// ---------------- scratch (device globals; no allocs allowed) ----------------
__device__ int    g_counts[E_];
__device__ int    g_cursors[E_];
__device__ int    g_offsets[E_];
__device__ int    g_ids_is32;
__device__ int    g_rowmap[TK_];                      // grouped pos -> flat slot (t*K+k)
__device__ __half g_act [(size_t)TK_ * I_];           // silu(gate)*up, grouped rows, fp16
__device__ float  g_ybuf[(size_t)TK_ * H_];           // per-slot weighted y

// ---------------- routing ----------------
__global__ void k_zero() {
    int i = threadIdx.x;
    if (i < E_) { g_counts[i] = 0; g_cursors[i] = 0; }
    if (i == 0) g_ids_is32 = 0;
}

// ids dtype detect: reads first TK_ int32 words (in-bounds for both layouts).
__global__ void k_detect(const int* __restrict__ idsv) {
    int any = 0;
    for (int i = threadIdx.x * 2 + 1; i < TK_; i += 2 * blockDim.x) any |= idsv[i];
    if (any) atomicOr(&g_ids_is32, 1);
}

__device__ __forceinline__ int load_id(const void* ids, int i, int is32) {
    return is32 ? ((const int*)ids)[i] : (int)((const long long*)ids)[i];
}

__global__ void k_count(const void* __restrict__ ids) {
    int i = blockIdx.x * blockDim.x + threadIdx.x;
    int is32 = g_ids_is32;
    if (i < TK_) atomicAdd(&g_counts[load_id(ids, i, is32)], 1);
}

__global__ void k_offsets() {
    if (threadIdx.x == 0) {
        int acc = 0;
        for (int e = 0; e < E_; e++) { g_offsets[e] = acc; acc += g_counts[e]; }
    }
}

__global__ void k_scatter(const void* __restrict__ ids) {
    int i = blockIdx.x * blockDim.x + threadIdx.x;
    int is32 = g_ids_is32;
    if (i < TK_) {
        int e = load_id(ids, i, is32);
        int pos = g_offsets[e] + atomicAdd(&g_cursors[e], 1);
        g_rowmap[pos] = i;
    }
}

// ---------------- fp16 mma helpers ----------------
__device__ __forceinline__ void mma16(float* d, const uint32_t* a, const uint32_t* b) {
    asm volatile(
        "mma.sync.aligned.m16n8k16.row.col.f32.f16.f16.f32 "
        "{%0,%1,%2,%3}, {%4,%5,%6,%7}, {%8,%9}, {%0,%1,%2,%3};"
        : "+f"(d[0]), "+f"(d[1]), "+f"(d[2]), "+f"(d[3])
        : "r"(a[0]), "r"(a[1]), "r"(a[2]), "r"(a[3]), "r"(b[0]), "r"(b[1]));
}

// convert float4 -> 4 fp16 -> 8 bytes in smem
__device__ __forceinline__ void cvt_store_h4(uint32_t* sdst, float4 v) {
    __half2 h0 = __floats2half2_rn(v.x, v.y);
    __half2 h1 = __floats2half2_rn(v.z, v.w);
    uint2 u;
    u.x = *reinterpret_cast<uint32_t*>(&h0);
    u.y = *reinterpret_cast<uint32_t*>(&h1);
    *reinterpret_cast<uint2*>(sdst) = u;
}

// ======================= GEMM13: act = silu(x Wg^T) * (x Wu^T) =======================
// BM=128, BN=128 (i-dim), BK=32 fp16. 256 threads, 8 warps (2m x 4n), warp tile 64x32.
// smem: 2 stages x (A + G + U) tiles, each 128 rows x STR_ words.
__global__ __launch_bounds__(256, 1)
void k_gemm13(const float* __restrict__ x, const float* __restrict__ w13) {
    extern __shared__ uint32_t sm[];
    const int e   = blockIdx.z;
    const int cnt = g_counts[e];
    const int m0  = blockIdx.y * 128;
    if (m0 >= cnt) return;
    const int off = g_offsets[e];
    const int n0  = blockIdx.x * 128;

    const float* wg = w13 + (size_t)e * (2 * I_) * H_ + (size_t)n0 * H_;
    const size_t UPOFF = (size_t)I_ * H_;

    const int tid  = threadIdx.x;
    const int warp = tid >> 5, lane = tid & 31;
    const int wm = (warp >> 2) * 64;
    const int wn = (warp & 3) * 32;

    // Producer mapping: 128 rows x 8 float4-chunks = 1024 chunks = 256 thr x 4
    const float* aptr[4]; const float* gptr[4]; int sw[4];
    #pragma unroll
    for (int j = 0; j < 4; j++) {
        int f = tid + j * 256;
        int r = f >> 3, c4 = f & 7;
        sw[j] = r * STR_ + c4 * 2;
        int pos = m0 + r;
        int idx = (pos < cnt) ? (off + pos) : off;
        int tok = g_rowmap[idx] >> 1;                 // K_=2
        aptr[j] = x + (size_t)tok * H_ + c4 * 4;
        gptr[j] = wg + (size_t)r * H_ + c4 * 4;
    }

    float gacc[4][4][4], uacc[4][4][4];
    #pragma unroll
    for (int a = 0; a < 4; a++)
        #pragma unroll
        for (int b = 0; b < 4; b++)
            #pragma unroll
            for (int c = 0; c < 4; c++) { gacc[a][b][c] = 0.f; uacc[a][b][c] = 0.f; }

    float4 ra[4], rg[4], ru[4];
    #pragma unroll
    for (int j = 0; j < 4; j++) {
        ra[j] = *reinterpret_cast<const float4*>(aptr[j]);
        rg[j] = *reinterpret_cast<const float4*>(gptr[j]);
        ru[j] = *reinterpret_cast<const float4*>(gptr[j] + UPOFF);
    }

    const int KT = H_ / BK_;                           // 64
    for (int kt = 0; kt < KT; kt++) {
        uint32_t* sA = sm + (kt & 1) * (3 * TILEW);
        uint32_t* sG = sA + TILEW;
        uint32_t* sU = sG + TILEW;

        #pragma unroll
        for (int j = 0; j < 4; j++) {
            cvt_store_h4(&sA[sw[j]], ra[j]);
            cvt_store_h4(&sG[sw[j]], rg[j]);
            cvt_store_h4(&sU[sw[j]], ru[j]);
        }
        __syncthreads();

        if (kt + 1 < KT) {
            int kk = (kt + 1) * BK_;
            #pragma unroll
            for (int j = 0; j < 4; j++) {
                ra[j] = *reinterpret_cast<const float4*>(aptr[j] + kk);
                rg[j] = *reinterpret_cast<const float4*>(gptr[j] + kk);
                ru[j] = *reinterpret_cast<const float4*>(gptr[j] + UPOFF + kk);
            }
        }

        #pragma unroll
        for (int ks = 0; ks < 2; ks++) {
            const int kw = ks * 8;                     // word offset of this k16 step
            uint32_t af[4][4];
            #pragma unroll
            for (int mf = 0; mf < 4; mf++) {
                int r = wm + mf * 16 + (lane >> 2);
                int c = kw + (lane & 3);
                af[mf][0] = sA[r * STR_ + c];
                af[mf][1] = sA[(r + 8) * STR_ + c];
                af[mf][2] = sA[r * STR_ + c + 4];
                af[mf][3] = sA[(r + 8) * STR_ + c + 4];
            }
            #pragma unroll
            for (int nf = 0; nf < 4; nf++) {
                int n = wn + nf * 8 + (lane >> 2);
                int c = kw + (lane & 3);
                uint32_t bg[2], bu[2];
                bg[0] = sG[n * STR_ + c]; bg[1] = sG[n * STR_ + c + 4];
                bu[0] = sU[n * STR_ + c]; bu[1] = sU[n * STR_ + c + 4];
                #pragma unroll
                for (int mf = 0; mf < 4; mf++) {
                    mma16(gacc[mf][nf], af[mf], bg);
                    mma16(uacc[mf][nf], af[mf], bu);
                }
            }
        }
        __syncthreads();
    }

    // Epilogue: act = silu(gate) * up -> g_act (fp16)
    const int rows_left = cnt - m0;
    #pragma unroll
    for (int mf = 0; mf < 4; mf++) {
        #pragma unroll
        for (int half = 0; half < 2; half++) {
            int r = wm + mf * 16 + (lane >> 2) + half * 8;
            if (r < rows_left) {
                size_t base = (size_t)(off + m0 + r) * I_ + n0 + wn;
                #pragma unroll
                for (int nf = 0; nf < 4; nf++) {
                    float g0 = gacc[mf][nf][half * 2 + 0];
                    float g1 = gacc[mf][nf][half * 2 + 1];
                    float u0 = uacc[mf][nf][half * 2 + 0];
                    float u1 = uacc[mf][nf][half * 2 + 1];
                    float a0 = g0 / (1.f + __expf(-g0)) * u0;
                    float a1 = g1 / (1.f + __expf(-g1)) * u1;
                    int c = nf * 8 + (lane & 3) * 2;
                    *reinterpret_cast<__half2*>(g_act + base + c) = __floats2half2_rn(a0, a1);
                }
            }
        }
    }
}

// ======================= GEMM2: ybuf[slot] = tw[slot] * (act @ w2^T) =================
// A: g_act grouped rows [cnt x I] fp16; B: w2[e] [H x I] fp32->fp16. BM=BN=128, BK=32.
__global__ __launch_bounds__(256, 1)
void k_gemm2(const float* __restrict__ w2, const float* __restrict__ tw) {
    extern __shared__ uint32_t sm[];
    const int e   = blockIdx.z;
    const int cnt = g_counts[e];
    const int m0  = blockIdx.y * 128;
    if (m0 >= cnt) return;
    const int off = g_offsets[e];
    const int n0  = blockIdx.x * 128;

    const float* wb = w2 + (size_t)e * H_ * I_ + (size_t)n0 * I_;

    const int tid  = threadIdx.x;
    const int warp = tid >> 5, lane = tid & 31;
    const int wm = (warp >> 2) * 64;
    const int wn = (warp & 3) * 32;

    // A producer (fp16 source): 128 rows x 4 uint4-chunks (8 halfs) = 512 = 256 x 2
    const __half* aptr[2]; int asw[2];
    #pragma unroll
    for (int j = 0; j < 2; j++) {
        int f = tid + j * 256;
        int r = f >> 2, c8 = f & 3;
        asw[j] = r * STR_ + c8 * 4;
        int pos = m0 + r;
        int row = (pos < cnt) ? (off + pos) : off;
        aptr[j] = g_act + (size_t)row * I_ + c8 * 8;
    }
    // B producer (fp32 source): 4 frags
    const float* bptr[4]; int bsw[4];
    #pragma unroll
    for (int j = 0; j < 4; j++) {
        int f = tid + j * 256;
        int r = f >> 3, c4 = f & 7;
        bsw[j] = r * STR_ + c4 * 2;
        bptr[j] = wb + (size_t)r * I_ + c4 * 4;
    }

    float acc[4][4][4];
    #pragma unroll
    for (int a = 0; a < 4; a++)
        #pragma unroll
        for (int b = 0; b < 4; b++)
            #pragma unroll
            for (int c = 0; c < 4; c++) acc[a][b][c] = 0.f;

    uint4 ra[2]; float4 rb[4];
    #pragma unroll
    for (int j = 0; j < 2; j++) ra[j] = *reinterpret_cast<const uint4*>(aptr[j]);
    #pragma unroll
    for (int j = 0; j < 4; j++) rb[j] = *reinterpret_cast<const float4*>(bptr[j]);

    const int KT = I_ / BK_;                           // 88
    for (int kt = 0; kt < KT; kt++) {
        uint32_t* sA = sm + (kt & 1) * (2 * TILEW);
        uint32_t* sB = sA + TILEW;

        #pragma unroll
        for (int j = 0; j < 2; j++) *reinterpret_cast<uint4*>(&sA[asw[j]]) = ra[j];
        #pragma unroll
        for (int j = 0; j < 4; j++) cvt_store_h4(&sB[bsw[j]], rb[j]);
        __syncthreads();

        if (kt + 1 < KT) {
            int kk = (kt + 1) * BK_;
            #pragma unroll
            for (int j = 0; j < 2; j++)
                ra[j] = *reinterpret_cast<const uint4*>(aptr[j] + kk);
            #pragma unroll
            for (int j = 0; j < 4; j++)
                rb[j] = *reinterpret_cast<const float4*>(bptr[j] + kk);
        }

        #pragma unroll
        for (int ks = 0; ks < 2; ks++) {
            const int kw = ks * 8;
            uint32_t af[4][4];
            #pragma unroll
            for (int mf = 0; mf < 4; mf++) {
                int r = wm + mf * 16 + (lane >> 2);
                int c = kw + (lane & 3);
                af[mf][0] = sA[r * STR_ + c];
                af[mf][1] = sA[(r + 8) * STR_ + c];
                af[mf][2] = sA[r * STR_ + c + 4];
                af[mf][3] = sA[(r + 8) * STR_ + c + 4];
            }
            #pragma unroll
            for (int nf = 0; nf < 4; nf++) {
                int n = wn + nf * 8 + (lane >> 2);
                int c = kw + (lane & 3);
                uint32_t bf[2];
                bf[0] = sB[n * STR_ + c]; bf[1] = sB[n * STR_ + c + 4];
                #pragma unroll
                for (int mf = 0; mf < 4; mf++) mma16(acc[mf][nf], af[mf], bf);
            }
        }
        __syncthreads();
    }

    const int rows_left = cnt - m0;
    #pragma unroll
    for (int mf = 0; mf < 4; mf++) {
        #pragma unroll
        for (int half = 0; half < 2; half++) {
            int r = wm + mf * 16 + (lane >> 2) + half * 8;
            if (r < rows_left) {
                int slot = g_rowmap[off + m0 + r];
                float w = tw[slot];
                size_t base = (size_t)slot * H_ + n0 + wn;
                #pragma unroll
                for (int nf = 0; nf < 4; nf++) {
                    float y0 = acc[mf][nf][half * 2 + 0] * w;
                    float y1 = acc[mf][nf][half * 2 + 1] * w;
                    int c = nf * 8 + (lane & 3) * 2;
                    *reinterpret_cast<float2*>(g_ybuf + base + c) = make_float2(y0, y1);
                }
            }
        }
    }
}

// ---------------- combine: out[t] = ybuf[2t] + ybuf[2t+1] ----------------
__global__ void k_combine(float* __restrict__ out) {
    int i = blockIdx.x * blockDim.x + threadIdx.x;
    const int HW4 = H_ / 4;
    if (i < T_ * HW4) {
        int t = i / HW4, h4 = i % HW4;
        const float4* yb = reinterpret_cast<const float4*>(g_ybuf);
        float4 y0 = yb[(size_t)(2 * t) * HW4 + h4];
        float4 y1 = yb[(size_t)(2 * t + 1) * HW4 + h4];
        float4 o;
        o.x = y0.x + y1.x; o.y = y0.y + y1.y; o.z = y0.z + y1.z; o.w = y0.w + y1.w;
        reinterpret_cast<float4*>(out)[i] = o;
    }
}

// ---------------- launch ----------------
extern "C" void kernel_launch(void* const* d_in, const int* in_sizes, int n_in,
                              void* d_out, int out_size) {
    const float* x   = (const float*)d_in[0];
    const float* w13 = (const float*)d_in[1];
    const float* w2  = (const float*)d_in[2];
    const float* tw  = (const float*)d_in[3];
    const void*  ids = d_in[4];
    float* out = (float*)d_out;

    const int smem13 = 2 * 3 * TILEW * 4;   // 61440 B
    const int smem2  = 2 * 2 * TILEW * 4;   // 40960 B
    cudaFuncSetAttribute(k_gemm13, cudaFuncAttributeMaxDynamicSharedMemorySize, smem13);
    cudaFuncSetAttribute(k_gemm2,  cudaFuncAttributeMaxDynamicSharedMemorySize, smem2);

    k_zero<<<1, 32>>>();
    k_detect<<<1, 256>>>((const int*)ids);
    k_count<<<TK_ / 256, 256>>>(ids);
    k_offsets<<<1, 32>>>();
    k_scatter<<<TK_ / 256, 256>>>(ids);

    dim3 g13(I_ / 128, TK_ / 128, E_);    // (22, 64, 8); inactive m-tiles exit early
    k_gemm13<<<g13, 256, smem13>>>(x, w13);

    dim3 g2(H_ / 128, TK_ / 128, E_);     // (16, 64, 8)
    k_gemm2<<<g2, 256, smem2>>>(w2, tw);

    k_combine<<<(T_ * (H_ / 4) + 255) / 256, 256>>>(out);
}

// round 5
// speedup vs baseline: 2.3132x; 1.0864x over previous
#include <cuda_runtime.h>
#include <cuda_fp16.h>
#include <cstdint>

// Problem constants
#define T_   4096
#define H_   2048
#define I_   2816
#define E_   8
#define K_   2
#define TK_  (T_ * K_)

#define BK_     32           // k per mainloop iter (fp16 elements)
#define STAGES  4
#define TILE_B  8192         // one 128x32 fp16 tile = 8KB

// ---------------- scratch (device globals; no allocs allowed) ----------------
__device__ int    g_counts[E_];
__device__ int    g_cursors[E_];
__device__ int    g_offsets[E_];
__device__ int    g_ids_is32;
__device__ int    g_rowmap[TK_];                       // grouped pos -> flat slot (t*K+k)
__device__ __half g_xh  [(size_t)T_ * H_];             // x in fp16
__device__ __half g_w13h[(size_t)E_ * 2 * I_ * H_];    // w13 in fp16
__device__ __half g_w2h [(size_t)E_ * H_ * I_];        // w2 in fp16
__device__ __half g_act [(size_t)TK_ * I_];            // silu(gate)*up, grouped rows, fp16
__device__ float  g_ybuf[(size_t)TK_ * H_];            // per-slot weighted y

// ---------------- routing ----------------
__global__ void k_zero() {
    int i = threadIdx.x;
    if (i < E_) { g_counts[i] = 0; g_cursors[i] = 0; }
    if (i == 0) g_ids_is32 = 0;
}

// ids dtype detect: reads first TK_ int32 words (in-bounds for both layouts).
__global__ void k_detect(const int* __restrict__ idsv) {
    int any = 0;
    for (int i = threadIdx.x * 2 + 1; i < TK_; i += 2 * blockDim.x) any |= idsv[i];
    if (any) atomicOr(&g_ids_is32, 1);
}

__device__ __forceinline__ int load_id(const void* ids, int i, int is32) {
    return is32 ? ((const int*)ids)[i] : (int)((const long long*)ids)[i];
}

__global__ void k_count(const void* __restrict__ ids) {
    int i = blockIdx.x * blockDim.x + threadIdx.x;
    int is32 = g_ids_is32;
    if (i < TK_) atomicAdd(&g_counts[load_id(ids, i, is32)], 1);
}

__global__ void k_offsets() {
    if (threadIdx.x == 0) {
        int acc = 0;
        for (int e = 0; e < E_; e++) { g_offsets[e] = acc; acc += g_counts[e]; }
    }
}

__global__ void k_scatter(const void* __restrict__ ids) {
    int i = blockIdx.x * blockDim.x + threadIdx.x;
    int is32 = g_ids_is32;
    if (i < TK_) {
        int e = load_id(ids, i, is32);
        int pos = g_offsets[e] + atomicAdd(&g_cursors[e], 1);
        g_rowmap[pos] = i;
    }
}

// ---------------- fp32 -> fp16 bulk convert ----------------
__global__ void k_cvt(const float4* __restrict__ src, uint2* __restrict__ dst, int n4) {
    int i = blockIdx.x * blockDim.x + threadIdx.x;
    if (i < n4) {
        float4 v = src[i];
        __half2 h0 = __floats2half2_rn(v.x, v.y);
        __half2 h1 = __floats2half2_rn(v.z, v.w);
        dst[i] = make_uint2(*reinterpret_cast<uint32_t*>(&h0),
                            *reinterpret_cast<uint32_t*>(&h1));
    }
}

// ---------------- mma / cp.async helpers ----------------
__device__ __forceinline__ void mma16(float* d, const uint32_t* a, const uint32_t* b) {
    asm volatile(
        "mma.sync.aligned.m16n8k16.row.col.f32.f16.f16.f32 "
        "{%0,%1,%2,%3}, {%4,%5,%6,%7}, {%8,%9}, {%0,%1,%2,%3};"
        : "+f"(d[0]), "+f"(d[1]), "+f"(d[2]), "+f"(d[3])
        : "r"(a[0]), "r"(a[1]), "r"(a[2]), "r"(a[3]), "r"(b[0]), "r"(b[1]));
}

__device__ __forceinline__ void cpa16(uint32_t smem_dst, const void* gsrc) {
    asm volatile("cp.async.cg.shared.global [%0], [%1], 16;"
                 :: "r"(smem_dst), "l"(gsrc) : "memory");
}
__device__ __forceinline__ void cpa_commit() {
    asm volatile("cp.async.commit_group;" ::: "memory");
}
template <int N>
__device__ __forceinline__ void cpa_wait() {
    asm volatile("cp.async.wait_group %0;" :: "n"(N) : "memory");
}

// Swizzled word index within a 128x32-half tile (16 words of 4B per row, 64B rows).
// 16B chunk ch at row r goes to chunk ch ^ ((r>>1)&3).  Conflict-free for the
// m16n8k16 fragment pattern (8 consecutive rows x 4 lanes -> 32 distinct banks).
__device__ __forceinline__ int idxsw(int r, int w) {
    return r * 16 + ((((w >> 2) ^ ((r >> 1) & 3)) << 2) | (w & 3));
}
// byte offset of 16B chunk (r, ch) for the producer
__device__ __forceinline__ int chunk_off(int r, int ch) {
    return r * 64 + ((ch ^ ((r >> 1) & 3)) << 4);
}

// ======================= GEMM13: act = silu(x Wg^T) * (x Wu^T) =======================
// BM=128, BN=128, BK=32. 256 threads, 8 warps (2m x 4n), warp tile 64x32 (x2 for g/u).
// smem: STAGES x (A + G + U) 8KB tiles = 96KB. cp.async 4-stage pipeline.
__global__ __launch_bounds__(256, 1)
void k_gemm13(float* unused) {
    extern __shared__ uint32_t sm[];
    const int e   = blockIdx.z;
    const int cnt = g_counts[e];
    const int m0  = blockIdx.y * 128;
    if (m0 >= cnt) return;
    const int off = g_offsets[e];
    const int n0  = blockIdx.x * 128;

    const uint32_t sb = (uint32_t)__cvta_generic_to_shared(sm);
    const int tid  = threadIdx.x;
    const int warp = tid >> 5, lane = tid & 31;
    const int wm = (warp >> 2) * 64;
    const int wn = (warp & 3) * 32;
    const int row0 = lane >> 2, c0 = lane & 3;

    // Producer: 512 chunks of 16B per tile, 2 per thread
    const __half* aS[2]; const __half* gS[2]; const __half* uS[2]; int doff[2];
    #pragma unroll
    for (int j = 0; j < 2; j++) {
        int f = tid + j * 256, r = f >> 2, ch = f & 3;
        doff[j] = chunk_off(r, ch);
        int pos = m0 + r;
        int idx = (pos < cnt) ? (off + pos) : off;
        int tok = g_rowmap[idx] >> 1;                 // K_=2
        aS[j] = g_xh + (size_t)tok * H_ + ch * 8;
        gS[j] = g_w13h + (size_t)e * (2 * I_) * H_ + (size_t)(n0 + r) * H_ + ch * 8;
        uS[j] = gS[j] + (size_t)I_ * H_;
    }

    const int KT = H_ / BK_;                           // 64
    auto issue = [&](int kt) {
        const int kk = kt * BK_;
        const uint32_t base = sb + (kt & (STAGES - 1)) * (3 * TILE_B);
        #pragma unroll
        for (int j = 0; j < 2; j++) {
            cpa16(base + doff[j],              aS[j] + kk);
            cpa16(base + TILE_B + doff[j],     gS[j] + kk);
            cpa16(base + 2 * TILE_B + doff[j], uS[j] + kk);
        }
    };

    float gacc[4][4][4], uacc[4][4][4];
    #pragma unroll
    for (int a = 0; a < 4; a++)
        #pragma unroll
        for (int b = 0; b < 4; b++)
            #pragma unroll
            for (int c = 0; c < 4; c++) { gacc[a][b][c] = 0.f; uacc[a][b][c] = 0.f; }

    #pragma unroll
    for (int s = 0; s < STAGES - 1; s++) { issue(s); cpa_commit(); }

    for (int kt = 0; kt < KT; kt++) {
        cpa_wait<STAGES - 2>();
        __syncthreads();
        if (kt + STAGES - 1 < KT) issue(kt + STAGES - 1);
        cpa_commit();

        const uint32_t* sA = sm + (kt & (STAGES - 1)) * (3 * TILE_B / 4);
        const uint32_t* sG = sA + TILE_B / 4;
        const uint32_t* sU = sG + TILE_B / 4;

        #pragma unroll
        for (int ks = 0; ks < 2; ks++) {
            const int kw = ks * 8;
            uint32_t af[4][4];
            #pragma unroll
            for (int mf = 0; mf < 4; mf++) {
                int r = wm + mf * 16 + row0;
                af[mf][0] = sA[idxsw(r,     kw + c0)];
                af[mf][1] = sA[idxsw(r + 8, kw + c0)];
                af[mf][2] = sA[idxsw(r,     kw + 4 + c0)];
                af[mf][3] = sA[idxsw(r + 8, kw + 4 + c0)];
            }
            #pragma unroll
            for (int nf = 0; nf < 4; nf++) {
                int n = wn + nf * 8 + row0;
                uint32_t bg[2], bu[2];
                bg[0] = sG[idxsw(n, kw + c0)]; bg[1] = sG[idxsw(n, kw + 4 + c0)];
                bu[0] = sU[idxsw(n, kw + c0)]; bu[1] = sU[idxsw(n, kw + 4 + c0)];
                #pragma unroll
                for (int mf = 0; mf < 4; mf++) {
                    mma16(gacc[mf][nf], af[mf], bg);
                    mma16(uacc[mf][nf], af[mf], bu);
                }
            }
        }
    }

    // Epilogue: act = silu(gate) * up -> g_act (fp16)
    const int rows_left = cnt - m0;
    #pragma unroll
    for (int mf = 0; mf < 4; mf++) {
        #pragma unroll
        for (int half = 0; half < 2; half++) {
            int r = wm + mf * 16 + row0 + half * 8;
            if (r < rows_left) {
                size_t base = (size_t)(off + m0 + r) * I_ + n0 + wn;
                #pragma unroll
                for (int nf = 0; nf < 4; nf++) {
                    float g0 = gacc[mf][nf][half * 2 + 0];
                    float g1 = gacc[mf][nf][half * 2 + 1];
                    float u0 = uacc[mf][nf][half * 2 + 0];
                    float u1 = uacc[mf][nf][half * 2 + 1];
                    float a0 = g0 / (1.f + __expf(-g0)) * u0;
                    float a1 = g1 / (1.f + __expf(-g1)) * u1;
                    int c = nf * 8 + c0 * 2;
                    *reinterpret_cast<__half2*>(g_act + base + c) = __floats2half2_rn(a0, a1);
                }
            }
        }
    }
}

// ======================= GEMM2: ybuf[slot] = tw[slot] * (act @ w2^T) =================
// A: g_act grouped rows [cnt x I] fp16; B: g_w2h [H x I] fp16. BM=BN=128, BK=32.
__global__ __launch_bounds__(256, 1)
void k_gemm2(const float* __restrict__ tw) {
    extern __shared__ uint32_t sm[];
    const int e   = blockIdx.z;
    const int cnt = g_counts[e];
    const int m0  = blockIdx.y * 128;
    if (m0 >= cnt) return;
    const int off = g_offsets[e];
    const int n0  = blockIdx.x * 128;

    const uint32_t sb = (uint32_t)__cvta_generic_to_shared(sm);
    const int tid  = threadIdx.x;
    const int warp = tid >> 5, lane = tid & 31;
    const int wm = (warp >> 2) * 64;
    const int wn = (warp & 3) * 32;
    const int row0 = lane >> 2, c0 = lane & 3;

    const __half* aS[2]; const __half* bS[2]; int doff[2];
    #pragma unroll
    for (int j = 0; j < 2; j++) {
        int f = tid + j * 256, r = f >> 2, ch = f & 3;
        doff[j] = chunk_off(r, ch);
        int pos = m0 + r;
        int row = (pos < cnt) ? (off + pos) : off;
        aS[j] = g_act + (size_t)row * I_ + ch * 8;
        bS[j] = g_w2h + (size_t)e * H_ * I_ + (size_t)(n0 + r) * I_ + ch * 8;
    }

    const int KT = I_ / BK_;                           // 88
    auto issue = [&](int kt) {
        const int kk = kt * BK_;
        const uint32_t base = sb + (kt & (STAGES - 1)) * (2 * TILE_B);
        #pragma unroll
        for (int j = 0; j < 2; j++) {
            cpa16(base + doff[j],          aS[j] + kk);
            cpa16(base + TILE_B + doff[j], bS[j] + kk);
        }
    };

    float acc[4][4][4];
    #pragma unroll
    for (int a = 0; a < 4; a++)
        #pragma unroll
        for (int b = 0; b < 4; b++)
            #pragma unroll
            for (int c = 0; c < 4; c++) acc[a][b][c] = 0.f;

    #pragma unroll
    for (int s = 0; s < STAGES - 1; s++) { issue(s); cpa_commit(); }

    for (int kt = 0; kt < KT; kt++) {
        cpa_wait<STAGES - 2>();
        __syncthreads();
        if (kt + STAGES - 1 < KT) issue(kt + STAGES - 1);
        cpa_commit();

        const uint32_t* sA = sm + (kt & (STAGES - 1)) * (2 * TILE_B / 4);
        const uint32_t* sB = sA + TILE_B / 4;

        #pragma unroll
        for (int ks = 0; ks < 2; ks++) {
            const int kw = ks * 8;
            uint32_t af[4][4];
            #pragma unroll
            for (int mf = 0; mf < 4; mf++) {
                int r = wm + mf * 16 + row0;
                af[mf][0] = sA[idxsw(r,     kw + c0)];
                af[mf][1] = sA[idxsw(r + 8, kw + c0)];
                af[mf][2] = sA[idxsw(r,     kw + 4 + c0)];
                af[mf][3] = sA[idxsw(r + 8, kw + 4 + c0)];
            }
            #pragma unroll
            for (int nf = 0; nf < 4; nf++) {
                int n = wn + nf * 8 + row0;
                uint32_t bf[2];
                bf[0] = sB[idxsw(n, kw + c0)]; bf[1] = sB[idxsw(n, kw + 4 + c0)];
                #pragma unroll
                for (int mf = 0; mf < 4; mf++) mma16(acc[mf][nf], af[mf], bf);
            }
        }
    }

    const int rows_left = cnt - m0;
    #pragma unroll
    for (int mf = 0; mf < 4; mf++) {
        #pragma unroll
        for (int half = 0; half < 2; half++) {
            int r = wm + mf * 16 + row0 + half * 8;
            if (r < rows_left) {
                int slot = g_rowmap[off + m0 + r];
                float w = tw[slot];
                size_t base = (size_t)slot * H_ + n0 + wn;
                #pragma unroll
                for (int nf = 0; nf < 4; nf++) {
                    float y0 = acc[mf][nf][half * 2 + 0] * w;
                    float y1 = acc[mf][nf][half * 2 + 1] * w;
                    int c = nf * 8 + c0 * 2;
                    *reinterpret_cast<float2*>(g_ybuf + base + c) = make_float2(y0, y1);
                }
            }
        }
    }
}

// ---------------- combine: out[t] = ybuf[2t] + ybuf[2t+1] ----------------
__global__ void k_combine(float* __restrict__ out) {
    int i = blockIdx.x * blockDim.x + threadIdx.x;
    const int HW4 = H_ / 4;
    if (i < T_ * HW4) {
        int t = i / HW4, h4 = i % HW4;
        const float4* yb = reinterpret_cast<const float4*>(g_ybuf);
        float4 y0 = yb[(size_t)(2 * t) * HW4 + h4];
        float4 y1 = yb[(size_t)(2 * t + 1) * HW4 + h4];
        float4 o;
        o.x = y0.x + y1.x; o.y = y0.y + y1.y; o.z = y0.z + y1.z; o.w = y0.w + y1.w;
        reinterpret_cast<float4*>(out)[i] = o;
    }
}

// ---------------- launch ----------------
extern "C" void kernel_launch(void* const* d_in, const int* in_sizes, int n_in,
                              void* d_out, int out_size) {
    const float* x   = (const float*)d_in[0];
    const float* w13 = (const float*)d_in[1];
    const float* w2  = (const float*)d_in[2];
    const float* tw  = (const float*)d_in[3];
    const void*  ids = d_in[4];
    float* out = (float*)d_out;

    const int smem13 = STAGES * 3 * TILE_B;   // 98304 B
    const int smem2  = STAGES * 2 * TILE_B;   // 65536 B
    cudaFuncSetAttribute(k_gemm13, cudaFuncAttributeMaxDynamicSharedMemorySize, smem13);
    cudaFuncSetAttribute(k_gemm2,  cudaFuncAttributeMaxDynamicSharedMemorySize, smem2);

    // routing
    k_zero<<<1, 32>>>();
    k_detect<<<1, 256>>>((const int*)ids);
    k_count<<<TK_ / 256, 256>>>(ids);
    k_offsets<<<1, 32>>>();
    k_scatter<<<TK_ / 256, 256>>>(ids);

    // fp16 conversion of inputs/weights
    {
        __half* xh; __half* w13h; __half* w2h;
        cudaGetSymbolAddress((void**)&xh,   g_xh);
        cudaGetSymbolAddress((void**)&w13h, g_w13h);
        cudaGetSymbolAddress((void**)&w2h,  g_w2h);
        int n4x  = T_ * H_ / 4;
        int n413 = E_ * 2 * I_ * H_ / 4;
        int n42  = E_ * H_ * I_ / 4;
        k_cvt<<<(n4x  + 255) / 256, 256>>>((const float4*)x,   (uint2*)xh,   n4x);
        k_cvt<<<(n413 + 255) / 256, 256>>>((const float4*)w13, (uint2*)w13h, n413);
        k_cvt<<<(n42  + 255) / 256, 256>>>((const float4*)w2,  (uint2*)w2h,  n42);
    }

    dim3 g13(I_ / 128, TK_ / 128, E_);    // (22, 64, 8); inactive m-tiles exit early
    k_gemm13<<<g13, 256, smem13>>>(nullptr);

    dim3 g2(H_ / 128, TK_ / 128, E_);     // (16, 64, 8)
    k_gemm2<<<g2, 256, smem2>>>(tw);

    k_combine<<<(T_ * (H_ / 4) + 255) / 256, 256>>>(out);
}

// round 6
// speedup vs baseline: 2.9053x; 1.2560x over previous
#include <cuda_runtime.h>
#include <cuda_fp16.h>
#include <cstdint>

// Problem constants
#define T_   4096
#define H_   2048
#define I_   2816
#define E_   8
#define K_   2
#define TK_  (T_ * K_)

#define BK_     32           // k per mainloop iter (fp16 elements)
#define STAGES  4
#define STAGE_B 16384        // bytes per stage (both gemms): 8K + 4K + 4K  /  8K + 8K

// ---------------- scratch (device globals; no allocs allowed) ----------------
__device__ int    g_counts[E_];
__device__ int    g_offsets[E_];
__device__ int    g_rowmap[TK_];                       // grouped pos -> flat slot (t*K+k)
__device__ __half g_xh  [(size_t)T_ * H_];             // x in fp16
__device__ __half g_w13h[(size_t)E_ * 2 * I_ * H_];    // w13 in fp16
__device__ __half g_w2h [(size_t)E_ * H_ * I_];        // w2 in fp16
__device__ __half g_act [(size_t)TK_ * I_];            // silu(gate)*up, grouped rows, fp16
__device__ float  g_ybuf[(size_t)TK_ * H_];            // per-slot weighted y

// ---------------- fused routing: detect dtype, count, prefix, scatter -------
__device__ __forceinline__ int load_id(const void* ids, int i, int is32) {
    return is32 ? ((const int*)ids)[i] : (int)((const long long*)ids)[i];
}

__global__ void k_route(const void* __restrict__ ids) {
    __shared__ int s_cnt[E_], s_cur[E_], s_off[E_];
    __shared__ int s_is32;
    const int tid = threadIdx.x;                       // 1024 threads
    if (tid == 0) s_is32 = 0;
    if (tid < E_) { s_cnt[tid] = 0; s_cur[tid] = 0; }
    __syncthreads();
    // dtype detect: odd int32 words all zero iff int64 little-endian values 0..7
    const int* idsv = (const int*)ids;
    int any = 0;
    for (int i = tid * 2 + 1; i < TK_; i += 2048) any |= idsv[i];
    if (any) atomicOr(&s_is32, 1);
    __syncthreads();
    const int is32 = s_is32;
    for (int i = tid; i < TK_; i += 1024)
        atomicAdd(&s_cnt[load_id(ids, i, is32)], 1);
    __syncthreads();
    if (tid == 0) {
        int acc = 0;
        for (int e = 0; e < E_; e++) { s_off[e] = acc; acc += s_cnt[e]; }
    }
    __syncthreads();
    for (int i = tid; i < TK_; i += 1024) {
        int e = load_id(ids, i, is32);
        int pos = s_off[e] + atomicAdd(&s_cur[e], 1);
        g_rowmap[pos] = i;
    }
    if (tid < E_) { g_counts[tid] = s_cnt[tid]; g_offsets[tid] = s_off[tid]; }
}

// ---------------- fp32 -> fp16 bulk converts (2 kernels) ----------------
__device__ __forceinline__ void cvt4(const float4* s, uint2* d, int i) {
    float4 v = s[i];
    __half2 h0 = __floats2half2_rn(v.x, v.y);
    __half2 h1 = __floats2half2_rn(v.z, v.w);
    d[i] = make_uint2(*reinterpret_cast<uint32_t*>(&h0),
                      *reinterpret_cast<uint32_t*>(&h1));
}

#define N4X  (T_ * H_ / 4)
#define N413 (E_ * 2 * I_ * H_ / 4)
#define N42  (E_ * H_ * I_ / 4)

__global__ void k_cvt_a(const float4* __restrict__ x, const float4* __restrict__ w13) {
    long long i = (long long)blockIdx.x * blockDim.x + threadIdx.x;
    if (i < N4X) cvt4(x, (uint2*)g_xh, (int)i);
    else if (i < (long long)N4X + N413) cvt4(w13, (uint2*)g_w13h, (int)(i - N4X));
}
__global__ void k_cvt_b(const float4* __restrict__ w2) {
    long long i = (long long)blockIdx.x * blockDim.x + threadIdx.x;
    if (i < N42) cvt4(w2, (uint2*)g_w2h, (int)i);
}

// ---------------- mma / cp.async / ldmatrix helpers ----------------
__device__ __forceinline__ void mma16(float* d, const uint32_t* a, const uint32_t* b) {
    asm volatile(
        "mma.sync.aligned.m16n8k16.row.col.f32.f16.f16.f32 "
        "{%0,%1,%2,%3}, {%4,%5,%6,%7}, {%8,%9}, {%0,%1,%2,%3};"
        : "+f"(d[0]), "+f"(d[1]), "+f"(d[2]), "+f"(d[3])
        : "r"(a[0]), "r"(a[1]), "r"(a[2]), "r"(a[3]), "r"(b[0]), "r"(b[1]));
}
__device__ __forceinline__ void cpa16(uint32_t smem_dst, const void* gsrc) {
    asm volatile("cp.async.cg.shared.global [%0], [%1], 16;"
                 :: "r"(smem_dst), "l"(gsrc) : "memory");
}
__device__ __forceinline__ void cpa_commit() {
    asm volatile("cp.async.commit_group;" ::: "memory");
}
template <int N>
__device__ __forceinline__ void cpa_wait() {
    asm volatile("cp.async.wait_group %0;" :: "n"(N) : "memory");
}
__device__ __forceinline__ void ldsm4(uint32_t* r, uint32_t addr) {
    asm volatile("ldmatrix.sync.aligned.m8n8.x4.shared.b16 {%0,%1,%2,%3}, [%4];"
                 : "=r"(r[0]), "=r"(r[1]), "=r"(r[2]), "=r"(r[3]) : "r"(addr));
}

// byte offset of 16B chunk (r, ch) in a 64B-row tile with XOR swizzle
__device__ __forceinline__ int chunk_off(int r, int ch) {
    return r * 64 + (((ch ^ ((r >> 1) & 3)) & 3) << 4);
}

// ======================= GEMM13: act = silu(x Wg^T) * (x Wu^T) =======================
// BM=128, BN=64 (g and u), BK=32. 256 thr, 8 warps as 4m x 2n, warp tile 32x32 (x2 g/u).
// smem/stage: A 8KB @0, G 4KB @8192, U 4KB @12288.  2 CTAs/SM.
__global__ __launch_bounds__(256, 2)
void k_gemm13(float* unused) {
    extern __shared__ uint32_t sm[];
    const int e   = blockIdx.z;
    const int cnt = g_counts[e];
    const int m0  = blockIdx.y * 128;
    if (m0 >= cnt) return;
    const int off = g_offsets[e];
    const int n0  = blockIdx.x * 64;

    const uint32_t sb = (uint32_t)__cvta_generic_to_shared(sm);
    const int tid  = threadIdx.x;
    const int warp = tid >> 5, lane = tid & 31;
    const int wm = (warp >> 1) * 32;          // 0,32,64,96
    const int wn = (warp & 1) * 32;           // 0,32
    const int row0 = lane >> 2, c0 = lane & 3;
    const int lrow = lane & 15, lch = lane >> 4;

    // ---- producer mappings ----
    const __half* aS[2]; int sAo[2];
    #pragma unroll
    for (int j = 0; j < 2; j++) {
        int f = tid + j * 256, r = f >> 2, ch = f & 3;
        sAo[j] = chunk_off(r, ch);
        int pos = m0 + r;
        int idx = (pos < cnt) ? (off + pos) : off;
        int tok = g_rowmap[idx] >> 1;          // K_=2
        aS[j] = g_xh + (size_t)tok * H_ + ch * 8;
    }
    const int gr = tid >> 2, gch = tid & 3;    // 64 rows x 4 chunks
    const int sGo = 8192 + chunk_off(gr, gch);
    const int sUo = 12288 + chunk_off(gr, gch);
    const __half* gS = g_w13h + (size_t)e * (2 * I_) * H_ + (size_t)(n0 + gr) * H_ + gch * 8;
    const __half* uS = gS + (size_t)I_ * H_;

    // ---- consumer ldmatrix lane offsets (within stage) ----
    int offA[2][2], offG[2][2], offU[2][2];
    #pragma unroll
    for (int ks = 0; ks < 2; ks++) {
        #pragma unroll
        for (int q = 0; q < 2; q++) {
            offA[q][ks] = chunk_off(wm + q * 16 + lrow, 2 * ks + lch);
            offG[q][ks] = 8192  + chunk_off(wn + q * 16 + lrow, 2 * ks + lch);
            offU[q][ks] = 12288 + chunk_off(wn + q * 16 + lrow, 2 * ks + lch);
        }
    }

    const int KT = H_ / BK_;                   // 64
    auto issue = [&](int kt) {
        const int kk = kt * BK_;
        const uint32_t base = sb + (kt & (STAGES - 1)) * STAGE_B;
        cpa16(base + sAo[0], aS[0] + kk);
        cpa16(base + sAo[1], aS[1] + kk);
        cpa16(base + sGo,    gS + kk);
        cpa16(base + sUo,    uS + kk);
    };

    float gacc[2][4][4], uacc[2][4][4];
    #pragma unroll
    for (int a = 0; a < 2; a++)
        #pragma unroll
        for (int b = 0; b < 4; b++)
            #pragma unroll
            for (int c = 0; c < 4; c++) { gacc[a][b][c] = 0.f; uacc[a][b][c] = 0.f; }

    #pragma unroll
    for (int s = 0; s < STAGES - 1; s++) { issue(s); cpa_commit(); }

    for (int kt = 0; kt < KT; kt++) {
        cpa_wait<STAGES - 2>();
        __syncthreads();
        if (kt + STAGES - 1 < KT) issue(kt + STAGES - 1);
        cpa_commit();

        const uint32_t base = sb + (kt & (STAGES - 1)) * STAGE_B;
        #pragma unroll
        for (int ks = 0; ks < 2; ks++) {
            uint32_t a0[4], a1[4];
            ldsm4(a0, base + offA[0][ks]);
            ldsm4(a1, base + offA[1][ks]);
            uint32_t gp0[4], gp1[4], up0[4], up1[4];
            ldsm4(gp0, base + offG[0][ks]);
            ldsm4(gp1, base + offG[1][ks]);
            ldsm4(up0, base + offU[0][ks]);
            ldsm4(up1, base + offU[1][ks]);
            // pair 0 -> nf 0,1 ; pair 1 -> nf 2,3
            #pragma unroll
            for (int p = 0; p < 2; p++) {
                const uint32_t* gp = p ? gp1 : gp0;
                const uint32_t* up = p ? up1 : up0;
                #pragma unroll
                for (int sub = 0; sub < 2; sub++) {
                    uint32_t bg[2] = { gp[sub], gp[sub + 2] };
                    uint32_t bu[2] = { up[sub], up[sub + 2] };
                    const int nf = 2 * p + sub;
                    mma16(gacc[0][nf], a0, bg);
                    mma16(gacc[1][nf], a1, bg);
                    mma16(uacc[0][nf], a0, bu);
                    mma16(uacc[1][nf], a1, bu);
                }
            }
        }
    }

    // Epilogue: act = silu(gate) * up -> g_act (fp16)
    const int rows_left = cnt - m0;
    #pragma unroll
    for (int mf = 0; mf < 2; mf++) {
        #pragma unroll
        for (int half = 0; half < 2; half++) {
            int r = wm + mf * 16 + row0 + half * 8;
            if (r < rows_left) {
                size_t base = (size_t)(off + m0 + r) * I_ + n0 + wn;
                #pragma unroll
                for (int nf = 0; nf < 4; nf++) {
                    float g0 = gacc[mf][nf][half * 2 + 0];
                    float g1 = gacc[mf][nf][half * 2 + 1];
                    float u0 = uacc[mf][nf][half * 2 + 0];
                    float u1 = uacc[mf][nf][half * 2 + 1];
                    float a0 = g0 / (1.f + __expf(-g0)) * u0;
                    float a1 = g1 / (1.f + __expf(-g1)) * u1;
                    int c = nf * 8 + c0 * 2;
                    *reinterpret_cast<__half2*>(g_act + base + c) = __floats2half2_rn(a0, a1);
                }
            }
        }
    }
}

// ======================= GEMM2: ybuf[slot] = tw[slot] * (act @ w2^T) =================
// BM=128, BN=128, BK=32. 8 warps as 2m x 4n, warp tile 64x32. smem/stage: A 8K + B 8K.
__global__ __launch_bounds__(256, 2)
void k_gemm2(const float* __restrict__ tw) {
    extern __shared__ uint32_t sm[];
    const int e   = blockIdx.z;
    const int cnt = g_counts[e];
    const int m0  = blockIdx.y * 128;
    if (m0 >= cnt) return;
    const int off = g_offsets[e];
    const int n0  = blockIdx.x * 128;

    const uint32_t sb = (uint32_t)__cvta_generic_to_shared(sm);
    const int tid  = threadIdx.x;
    const int warp = tid >> 5, lane = tid & 31;
    const int wm = (warp >> 2) * 64;          // 0,64
    const int wn = (warp & 3) * 32;           // 0..96
    const int row0 = lane >> 2, c0 = lane & 3;
    const int lrow = lane & 15, lch = lane >> 4;

    // ---- producers ----
    const __half* aS[2]; int sAo[2];
    const __half* bS[2]; int sBo[2];
    #pragma unroll
    for (int j = 0; j < 2; j++) {
        int f = tid + j * 256, r = f >> 2, ch = f & 3;
        sAo[j] = chunk_off(r, ch);
        sBo[j] = 8192 + chunk_off(r, ch);
        int pos = m0 + r;
        int row = (pos < cnt) ? (off + pos) : off;
        aS[j] = g_act + (size_t)row * I_ + ch * 8;
        bS[j] = g_w2h + (size_t)e * H_ * I_ + (size_t)(n0 + r) * I_ + ch * 8;
    }

    // ---- ldmatrix lane offsets ----
    int offA[4][2], offB[2][2];
    #pragma unroll
    for (int ks = 0; ks < 2; ks++) {
        #pragma unroll
        for (int mf = 0; mf < 4; mf++)
            offA[mf][ks] = chunk_off(wm + mf * 16 + lrow, 2 * ks + lch);
        #pragma unroll
        for (int p = 0; p < 2; p++)
            offB[p][ks] = 8192 + chunk_off(wn + p * 16 + lrow, 2 * ks + lch);
    }

    const int KT = I_ / BK_;                   // 88
    auto issue = [&](int kt) {
        const int kk = kt * BK_;
        const uint32_t base = sb + (kt & (STAGES - 1)) * STAGE_B;
        cpa16(base + sAo[0], aS[0] + kk);
        cpa16(base + sAo[1], aS[1] + kk);
        cpa16(base + sBo[0], bS[0] + kk);
        cpa16(base + sBo[1], bS[1] + kk);
    };

    float acc[4][4][4];
    #pragma unroll
    for (int a = 0; a < 4; a++)
        #pragma unroll
        for (int b = 0; b < 4; b++)
            #pragma unroll
            for (int c = 0; c < 4; c++) acc[a][b][c] = 0.f;

    #pragma unroll
    for (int s = 0; s < STAGES - 1; s++) { issue(s); cpa_commit(); }

    for (int kt = 0; kt < KT; kt++) {
        cpa_wait<STAGES - 2>();
        __syncthreads();
        if (kt + STAGES - 1 < KT) issue(kt + STAGES - 1);
        cpa_commit();

        const uint32_t base = sb + (kt & (STAGES - 1)) * STAGE_B;
        #pragma unroll
        for (int ks = 0; ks < 2; ks++) {
            uint32_t af[4][4];
            #pragma unroll
            for (int mf = 0; mf < 4; mf++) ldsm4(af[mf], base + offA[mf][ks]);
            uint32_t bp0[4], bp1[4];
            ldsm4(bp0, base + offB[0][ks]);
            ldsm4(bp1, base + offB[1][ks]);
            #pragma unroll
            for (int p = 0; p < 2; p++) {
                const uint32_t* bp = p ? bp1 : bp0;
                #pragma unroll
                for (int sub = 0; sub < 2; sub++) {
                    uint32_t bf[2] = { bp[sub], bp[sub + 2] };
                    const int nf = 2 * p + sub;
                    #pragma unroll
                    for (int mf = 0; mf < 4; mf++) mma16(acc[mf][nf], af[mf], bf);
                }
            }
        }
    }

    const int rows_left = cnt - m0;
    #pragma unroll
    for (int mf = 0; mf < 4; mf++) {
        #pragma unroll
        for (int half = 0; half < 2; half++) {
            int r = wm + mf * 16 + row0 + half * 8;
            if (r < rows_left) {
                int slot = g_rowmap[off + m0 + r];
                float w = tw[slot];
                size_t base = (size_t)slot * H_ + n0 + wn;
                #pragma unroll
                for (int nf = 0; nf < 4; nf++) {
                    float y0 = acc[mf][nf][half * 2 + 0] * w;
                    float y1 = acc[mf][nf][half * 2 + 1] * w;
                    int c = nf * 8 + c0 * 2;
                    *reinterpret_cast<float2*>(g_ybuf + base + c) = make_float2(y0, y1);
                }
            }
        }
    }
}

// ---------------- combine: out[t] = ybuf[2t] + ybuf[2t+1] ----------------
__global__ void k_combine(float* __restrict__ out) {
    int i = blockIdx.x * blockDim.x + threadIdx.x;
    const int HW4 = H_ / 4;
    if (i < T_ * HW4) {
        int t = i / HW4, h4 = i % HW4;
        const float4* yb = reinterpret_cast<const float4*>(g_ybuf);
        float4 y0 = yb[(size_t)(2 * t) * HW4 + h4];
        float4 y1 = yb[(size_t)(2 * t + 1) * HW4 + h4];
        float4 o;
        o.x = y0.x + y1.x; o.y = y0.y + y1.y; o.z = y0.z + y1.z; o.w = y0.w + y1.w;
        reinterpret_cast<float4*>(out)[i] = o;
    }
}

// ---------------- launch ----------------
extern "C" void kernel_launch(void* const* d_in, const int* in_sizes, int n_in,
                              void* d_out, int out_size) {
    const float* x   = (const float*)d_in[0];
    const float* w13 = (const float*)d_in[1];
    const float* w2  = (const float*)d_in[2];
    const float* tw  = (const float*)d_in[3];
    const void*  ids = d_in[4];
    float* out = (float*)d_out;

    const int smem = STAGES * STAGE_B;        // 65536 B per CTA
    cudaFuncSetAttribute(k_gemm13, cudaFuncAttributeMaxDynamicSharedMemorySize, smem);
    cudaFuncSetAttribute(k_gemm2,  cudaFuncAttributeMaxDynamicSharedMemorySize, smem);

    // launch idx 0: routing (fused)
    k_route<<<1, 1024>>>(ids);
    // idx 1,2: fp16 converts
    k_cvt_a<<<(N4X + N413 + 255) / 256, 256>>>((const float4*)x, (const float4*)w13);
    k_cvt_b<<<(N42 + 255) / 256, 256>>>((const float4*)w2);
    // idx 3: gemm13  (ncu capture lands here)
    dim3 g13(I_ / 64, TK_ / 128, E_);         // (44, 64, 8); inactive m-tiles exit early
    k_gemm13<<<g13, 256, smem>>>(nullptr);
    // idx 4: gemm2
    dim3 g2(H_ / 128, TK_ / 128, E_);         // (16, 64, 8)
    k_gemm2<<<g2, 256, smem>>>(tw);
    // idx 5: combine
    k_combine<<<(T_ * (H_ / 4) + 255) / 256, 256>>>(out);
}

// round 7
// speedup vs baseline: 2.9608x; 1.0191x over previous
#include <cuda_runtime.h>
#include <cuda_fp16.h>
#include <cstdint>

// Problem constants
#define T_   4096
#define H_   2048
#define I_   2816
#define E_   8
#define K_   2
#define TK_  (T_ * K_)

#define BK_     64           // k per mainloop iter (fp16 elements) = 128B row
#define STAGES  3
#define STAGE_B 32768        // bytes per stage: 16K + 8K + 8K  /  16K + 16K

// ---------------- scratch (device globals; no allocs allowed) ----------------
__device__ int    g_counts[E_];
__device__ int    g_offsets[E_];
__device__ int    g_rowmap[TK_];                       // grouped pos -> flat slot (t*K+k)
__device__ __half g_xh  [(size_t)T_ * H_];             // x in fp16
__device__ __half g_w13h[(size_t)E_ * 2 * I_ * H_];    // w13 in fp16
__device__ __half g_w2h [(size_t)E_ * H_ * I_];        // w2 in fp16
__device__ __half g_act [(size_t)TK_ * I_];            // silu(gate)*up, grouped rows, fp16
__device__ float  g_ybuf[(size_t)TK_ * H_];            // per-slot weighted y

// ---------------- fused routing: detect dtype, count, prefix, scatter -------
__device__ __forceinline__ int load_id(const void* ids, int i, int is32) {
    return is32 ? ((const int*)ids)[i] : (int)((const long long*)ids)[i];
}

__global__ void k_route(const void* __restrict__ ids) {
    __shared__ int s_cnt[E_], s_cur[E_], s_off[E_];
    __shared__ int s_is32;
    const int tid = threadIdx.x;                       // 1024 threads
    if (tid == 0) s_is32 = 0;
    if (tid < E_) { s_cnt[tid] = 0; s_cur[tid] = 0; }
    __syncthreads();
    const int* idsv = (const int*)ids;
    int any = 0;
    for (int i = tid * 2 + 1; i < TK_; i += 2048) any |= idsv[i];
    if (any) atomicOr(&s_is32, 1);
    __syncthreads();
    const int is32 = s_is32;
    for (int i = tid; i < TK_; i += 1024)
        atomicAdd(&s_cnt[load_id(ids, i, is32)], 1);
    __syncthreads();
    if (tid == 0) {
        int acc = 0;
        for (int e = 0; e < E_; e++) { s_off[e] = acc; acc += s_cnt[e]; }
    }
    __syncthreads();
    for (int i = tid; i < TK_; i += 1024) {
        int e = load_id(ids, i, is32);
        int pos = s_off[e] + atomicAdd(&s_cur[e], 1);
        g_rowmap[pos] = i;
    }
    if (tid < E_) { g_counts[tid] = s_cnt[tid]; g_offsets[tid] = s_off[tid]; }
}

// ---------------- fp32 -> fp16 bulk converts (2 kernels) ----------------
__device__ __forceinline__ void cvt4(const float4* s, uint2* d, int i) {
    float4 v = s[i];
    __half2 h0 = __floats2half2_rn(v.x, v.y);
    __half2 h1 = __floats2half2_rn(v.z, v.w);
    d[i] = make_uint2(*reinterpret_cast<uint32_t*>(&h0),
                      *reinterpret_cast<uint32_t*>(&h1));
}

#define N4X  (T_ * H_ / 4)
#define N413 (E_ * 2 * I_ * H_ / 4)
#define N42  (E_ * H_ * I_ / 4)

__global__ void k_cvt_a(const float4* __restrict__ x, const float4* __restrict__ w13) {
    long long i = (long long)blockIdx.x * blockDim.x + threadIdx.x;
    if (i < N4X) cvt4(x, (uint2*)g_xh, (int)i);
    else if (i < (long long)N4X + N413) cvt4(w13, (uint2*)g_w13h, (int)(i - N4X));
}
__global__ void k_cvt_b(const float4* __restrict__ w2) {
    long long i = (long long)blockIdx.x * blockDim.x + threadIdx.x;
    if (i < N42) cvt4(w2, (uint2*)g_w2h, (int)i);
}

// ---------------- mma / cp.async / ldmatrix helpers ----------------
__device__ __forceinline__ void mma16(float* d, const uint32_t* a, const uint32_t* b) {
    asm volatile(
        "mma.sync.aligned.m16n8k16.row.col.f32.f16.f16.f32 "
        "{%0,%1,%2,%3}, {%4,%5,%6,%7}, {%8,%9}, {%0,%1,%2,%3};"
        : "+f"(d[0]), "+f"(d[1]), "+f"(d[2]), "+f"(d[3])
        : "r"(a[0]), "r"(a[1]), "r"(a[2]), "r"(a[3]), "r"(b[0]), "r"(b[1]));
}
__device__ __forceinline__ void cpa16(uint32_t smem_dst, const void* gsrc) {
    asm volatile("cp.async.cg.shared.global [%0], [%1], 16;"
                 :: "r"(smem_dst), "l"(gsrc) : "memory");
}
__device__ __forceinline__ void cpa_commit() {
    asm volatile("cp.async.commit_group;" ::: "memory");
}
template <int N>
__device__ __forceinline__ void cpa_wait() {
    asm volatile("cp.async.wait_group %0;" :: "n"(N) : "memory");
}
__device__ __forceinline__ void ldsm4(uint32_t* r, uint32_t addr) {
    asm volatile("ldmatrix.sync.aligned.m8n8.x4.shared.b16 {%0,%1,%2,%3}, [%4];"
                 : "=r"(r[0]), "=r"(r[1]), "=r"(r[2]), "=r"(r[3]) : "r"(addr));
}

// byte offset of 16B chunk (r, ch) in a 128B-row tile, SW128 swizzle (ch ^= r&7)
__device__ __forceinline__ int chunk_off(int r, int ch) {
    return r * 128 + (((ch ^ (r & 7)) & 7) << 4);
}

// ======================= GEMM13: act = silu(x Wg^T) * (x Wu^T) =======================
// BM=128, BN=64 (g and u), BK=64. 256 thr, 8 warps as 4m x 2n, warp tile 32x32 (x2 g/u).
// smem/stage: A 16KB @0, G 8KB @16384, U 8KB @24576.  3 stages, 2 CTAs/SM.
__global__ __launch_bounds__(256, 2)
void k_gemm13(float* unused) {
    extern __shared__ uint32_t sm[];
    const int e   = blockIdx.z;
    const int cnt = g_counts[e];
    const int m0  = blockIdx.y * 128;
    if (m0 >= cnt) return;
    const int off = g_offsets[e];
    const int n0  = blockIdx.x * 64;

    const uint32_t sb = (uint32_t)__cvta_generic_to_shared(sm);
    const int tid  = threadIdx.x;
    const int warp = tid >> 5, lane = tid & 31;
    const int wm = (warp >> 1) * 32;          // 0,32,64,96
    const int wn = (warp & 1) * 32;           // 0,32
    const int row0 = lane >> 2, c0 = lane & 3;
    const int lrow = lane & 15, lch = lane >> 4;

    // ---- producer mappings (chunks of 16B; row r, chunk ch in 0..7) ----
    // A: 128 rows x 8 chunks = 1024 -> 4 per thread
    const __half* aS[4]; int sAo[4];
    #pragma unroll
    for (int j = 0; j < 4; j++) {
        int f = tid + j * 256, r = f >> 3, ch = f & 7;
        sAo[j] = chunk_off(r, ch);
        int pos = m0 + r;
        int idx = (pos < cnt) ? (off + pos) : off;
        int tok = g_rowmap[idx] >> 1;          // K_=2
        aS[j] = g_xh + (size_t)tok * H_ + ch * 8;
    }
    // G/U: 64 rows x 8 chunks = 512 -> 2 per thread each
    const __half* gS[2]; const __half* uS[2]; int sGo[2], sUo[2];
    #pragma unroll
    for (int j = 0; j < 2; j++) {
        int f = tid + j * 256, r = f >> 3, ch = f & 7;
        sGo[j] = 16384 + chunk_off(r, ch);
        sUo[j] = 24576 + chunk_off(r, ch);
        gS[j] = g_w13h + (size_t)e * (2 * I_) * H_ + (size_t)(n0 + r) * H_ + ch * 8;
        uS[j] = gS[j] + (size_t)I_ * H_;
    }

    // ---- consumer ldmatrix lane offsets (within stage), ks = 0..3 ----
    int offA[2][4], offG[2][4], offU[2][4];
    #pragma unroll
    for (int ks = 0; ks < 4; ks++) {
        #pragma unroll
        for (int q = 0; q < 2; q++) {
            offA[q][ks] = chunk_off(wm + q * 16 + lrow, 2 * ks + lch);
            offG[q][ks] = 16384 + chunk_off(wn + q * 16 + lrow, 2 * ks + lch);
            offU[q][ks] = 24576 + chunk_off(wn + q * 16 + lrow, 2 * ks + lch);
        }
    }

    const int KT = H_ / BK_;                   // 32
    auto issue = [&](int kt, int st) {
        const int kk = kt * BK_;
        const uint32_t base = sb + st * STAGE_B;
        #pragma unroll
        for (int j = 0; j < 4; j++) cpa16(base + sAo[j], aS[j] + kk);
        #pragma unroll
        for (int j = 0; j < 2; j++) {
            cpa16(base + sGo[j], gS[j] + kk);
            cpa16(base + sUo[j], uS[j] + kk);
        }
    };

    float gacc[2][4][4], uacc[2][4][4];
    #pragma unroll
    for (int a = 0; a < 2; a++)
        #pragma unroll
        for (int b = 0; b < 4; b++)
            #pragma unroll
            for (int c = 0; c < 4; c++) { gacc[a][b][c] = 0.f; uacc[a][b][c] = 0.f; }

    issue(0, 0); cpa_commit();
    issue(1, 1); cpa_commit();

    int si = 2, ci = 0;                        // issue / compute stage indices
    for (int kt = 0; kt < KT; kt++) {
        cpa_wait<STAGES - 2>();
        __syncthreads();
        if (kt + 2 < KT) issue(kt + 2, si);
        cpa_commit();
        if (++si == STAGES) si = 0;

        const uint32_t base = sb + ci * STAGE_B;
        if (++ci == STAGES) ci = 0;
        #pragma unroll
        for (int ks = 0; ks < 4; ks++) {
            uint32_t a0[4], a1[4];
            ldsm4(a0, base + offA[0][ks]);
            ldsm4(a1, base + offA[1][ks]);
            uint32_t gp0[4], gp1[4], up0[4], up1[4];
            ldsm4(gp0, base + offG[0][ks]);
            ldsm4(gp1, base + offG[1][ks]);
            ldsm4(up0, base + offU[0][ks]);
            ldsm4(up1, base + offU[1][ks]);
            #pragma unroll
            for (int p = 0; p < 2; p++) {
                const uint32_t* gp = p ? gp1 : gp0;
                const uint32_t* up = p ? up1 : up0;
                #pragma unroll
                for (int sub = 0; sub < 2; sub++) {
                    uint32_t bg[2] = { gp[sub], gp[sub + 2] };
                    uint32_t bu[2] = { up[sub], up[sub + 2] };
                    const int nf = 2 * p + sub;
                    mma16(gacc[0][nf], a0, bg);
                    mma16(gacc[1][nf], a1, bg);
                    mma16(uacc[0][nf], a0, bu);
                    mma16(uacc[1][nf], a1, bu);
                }
            }
        }
    }

    // Epilogue: act = silu(gate) * up -> g_act (fp16)
    const int rows_left = cnt - m0;
    #pragma unroll
    for (int mf = 0; mf < 2; mf++) {
        #pragma unroll
        for (int half = 0; half < 2; half++) {
            int r = wm + mf * 16 + row0 + half * 8;
            if (r < rows_left) {
                size_t base = (size_t)(off + m0 + r) * I_ + n0 + wn;
                #pragma unroll
                for (int nf = 0; nf < 4; nf++) {
                    float g0 = gacc[mf][nf][half * 2 + 0];
                    float g1 = gacc[mf][nf][half * 2 + 1];
                    float u0 = uacc[mf][nf][half * 2 + 0];
                    float u1 = uacc[mf][nf][half * 2 + 1];
                    float a0 = g0 / (1.f + __expf(-g0)) * u0;
                    float a1 = g1 / (1.f + __expf(-g1)) * u1;
                    int c = nf * 8 + c0 * 2;
                    *reinterpret_cast<__half2*>(g_act + base + c) = __floats2half2_rn(a0, a1);
                }
            }
        }
    }
}

// ======================= GEMM2: ybuf[slot] = tw[slot] * (act @ w2^T) =================
// BM=128, BN=128, BK=64. 8 warps as 2m x 4n, warp tile 64x32. smem/stage: A 16K + B 16K.
__global__ __launch_bounds__(256, 2)
void k_gemm2(const float* __restrict__ tw) {
    extern __shared__ uint32_t sm[];
    const int e   = blockIdx.z;
    const int cnt = g_counts[e];
    const int m0  = blockIdx.y * 128;
    if (m0 >= cnt) return;
    const int off = g_offsets[e];
    const int n0  = blockIdx.x * 128;

    const uint32_t sb = (uint32_t)__cvta_generic_to_shared(sm);
    const int tid  = threadIdx.x;
    const int warp = tid >> 5, lane = tid & 31;
    const int wm = (warp >> 2) * 64;          // 0,64
    const int wn = (warp & 3) * 32;           // 0..96
    const int row0 = lane >> 2, c0 = lane & 3;
    const int lrow = lane & 15, lch = lane >> 4;

    // ---- producers: A and B each 128 rows x 8 chunks -> 4 per thread ----
    const __half* aS[4]; int sAo[4];
    const __half* bS[4]; int sBo[4];
    #pragma unroll
    for (int j = 0; j < 4; j++) {
        int f = tid + j * 256, r = f >> 3, ch = f & 7;
        sAo[j] = chunk_off(r, ch);
        sBo[j] = 16384 + chunk_off(r, ch);
        int pos = m0 + r;
        int row = (pos < cnt) ? (off + pos) : off;
        aS[j] = g_act + (size_t)row * I_ + ch * 8;
        bS[j] = g_w2h + (size_t)e * H_ * I_ + (size_t)(n0 + r) * I_ + ch * 8;
    }

    // ---- ldmatrix lane offsets ----
    int offA[4][4], offB[2][4];
    #pragma unroll
    for (int ks = 0; ks < 4; ks++) {
        #pragma unroll
        for (int mf = 0; mf < 4; mf++)
            offA[mf][ks] = chunk_off(wm + mf * 16 + lrow, 2 * ks + lch);
        #pragma unroll
        for (int p = 0; p < 2; p++)
            offB[p][ks] = 16384 + chunk_off(wn + p * 16 + lrow, 2 * ks + lch);
    }

    const int KT = I_ / BK_;                   // 44
    auto issue = [&](int kt, int st) {
        const int kk = kt * BK_;
        const uint32_t base = sb + st * STAGE_B;
        #pragma unroll
        for (int j = 0; j < 4; j++) {
            cpa16(base + sAo[j], aS[j] + kk);
            cpa16(base + sBo[j], bS[j] + kk);
        }
    };

    float acc[4][4][4];
    #pragma unroll
    for (int a = 0; a < 4; a++)
        #pragma unroll
        for (int b = 0; b < 4; b++)
            #pragma unroll
            for (int c = 0; c < 4; c++) acc[a][b][c] = 0.f;

    issue(0, 0); cpa_commit();
    issue(1, 1); cpa_commit();

    int si = 2, ci = 0;
    for (int kt = 0; kt < KT; kt++) {
        cpa_wait<STAGES - 2>();
        __syncthreads();
        if (kt + 2 < KT) issue(kt + 2, si);
        cpa_commit();
        if (++si == STAGES) si = 0;

        const uint32_t base = sb + ci * STAGE_B;
        if (++ci == STAGES) ci = 0;
        #pragma unroll
        for (int ks = 0; ks < 4; ks++) {
            uint32_t af[4][4];
            #pragma unroll
            for (int mf = 0; mf < 4; mf++) ldsm4(af[mf], base + offA[mf][ks]);
            uint32_t bp0[4], bp1[4];
            ldsm4(bp0, base + offB[0][ks]);
            ldsm4(bp1, base + offB[1][ks]);
            #pragma unroll
            for (int p = 0; p < 2; p++) {
                const uint32_t* bp = p ? bp1 : bp0;
                #pragma unroll
                for (int sub = 0; sub < 2; sub++) {
                    uint32_t bf[2] = { bp[sub], bp[sub + 2] };
                    const int nf = 2 * p + sub;
                    #pragma unroll
                    for (int mf = 0; mf < 4; mf++) mma16(acc[mf][nf], af[mf], bf);
                }
            }
        }
    }

    const int rows_left = cnt - m0;
    #pragma unroll
    for (int mf = 0; mf < 4; mf++) {
        #pragma unroll
        for (int half = 0; half < 2; half++) {
            int r = wm + mf * 16 + row0 + half * 8;
            if (r < rows_left) {
                int slot = g_rowmap[off + m0 + r];
                float w = tw[slot];
                size_t base = (size_t)slot * H_ + n0 + wn;
                #pragma unroll
                for (int nf = 0; nf < 4; nf++) {
                    float y0 = acc[mf][nf][half * 2 + 0] * w;
                    float y1 = acc[mf][nf][half * 2 + 1] * w;
                    int c = nf * 8 + c0 * 2;
                    *reinterpret_cast<float2*>(g_ybuf + base + c) = make_float2(y0, y1);
                }
            }
        }
    }
}

// ---------------- combine: out[t] = ybuf[2t] + ybuf[2t+1] ----------------
__global__ void k_combine(float* __restrict__ out) {
    int i = blockIdx.x * blockDim.x + threadIdx.x;
    const int HW4 = H_ / 4;
    if (i < T_ * HW4) {
        int t = i / HW4, h4 = i % HW4;
        const float4* yb = reinterpret_cast<const float4*>(g_ybuf);
        float4 y0 = yb[(size_t)(2 * t) * HW4 + h4];
        float4 y1 = yb[(size_t)(2 * t + 1) * HW4 + h4];
        float4 o;
        o.x = y0.x + y1.x; o.y = y0.y + y1.y; o.z = y0.z + y1.z; o.w = y0.w + y1.w;
        reinterpret_cast<float4*>(out)[i] = o;
    }
}

// ---------------- launch ----------------
extern "C" void kernel_launch(void* const* d_in, const int* in_sizes, int n_in,
                              void* d_out, int out_size) {
    const float* x   = (const float*)d_in[0];
    const float* w13 = (const float*)d_in[1];
    const float* w2  = (const float*)d_in[2];
    const float* tw  = (const float*)d_in[3];
    const void*  ids = d_in[4];
    float* out = (float*)d_out;

    const int smem = STAGES * STAGE_B;        // 98304 B per CTA
    cudaFuncSetAttribute(k_gemm13, cudaFuncAttributeMaxDynamicSharedMemorySize, smem);
    cudaFuncSetAttribute(k_gemm2,  cudaFuncAttributeMaxDynamicSharedMemorySize, smem);

    // idx 0: routing (fused)
    k_route<<<1, 1024>>>(ids);
    // idx 1,2: fp16 converts
    k_cvt_a<<<(N4X + N413 + 255) / 256, 256>>>((const float4*)x, (const float4*)w13);
    k_cvt_b<<<(N42 + 255) / 256, 256>>>((const float4*)w2);
    // idx 3: gemm13  (ncu capture lands here)
    dim3 g13(I_ / 64, TK_ / 128, E_);         // (44, 64, 8); inactive m-tiles exit early
    k_gemm13<<<g13, 256, smem>>>(nullptr);
    // idx 4: gemm2
    dim3 g2(H_ / 128, TK_ / 128, E_);         // (16, 64, 8)
    k_gemm2<<<g2, 256, smem>>>(tw);
    // idx 5: combine
    k_combine<<<(T_ * (H_ / 4) + 255) / 256, 256>>>(out);
}